// round 1
// baseline (speedup 1.0000x reference)
#include <cuda_runtime.h>
#include <cuda_bf16.h>
#include <stdint.h>

#define COLS 1024
#define CPC 8
#define NCELLS 8192            // COLS * CPC
#define THRESH 13.0f
#define PERM_CONN 0.5f

__device__ int g_prev_has;

// ---------------------------------------------------------------------------
// K1: new_active + anomaly + prev_has flag.
// 1 block, 1024 threads (one per column).
// out layout: [0:8192) new_active, [8192:16384) new_predictive,
//             [16384] anomaly, [16385:16385+64M) new_segment_weights
// ---------------------------------------------------------------------------
__global__ void tm_small_kernel(const float* __restrict__ active_columns,
                                const float* __restrict__ predictive_cells,
                                const float* __restrict__ prev_active,
                                float* __restrict__ out) {
    int c = threadIdx.x;  // column id, 0..1023

    float pred[CPC];
    float psum = 0.f;
#pragma unroll
    for (int k = 0; k < CPC; k++) {
        pred[k] = predictive_cells[c * CPC + k];
        psum += pred[k];
    }
    bool has_pred = psum > 0.f;
    bool am = active_columns[c] > 0.f;

#pragma unroll
    for (int k = 0; k < CPC; k++) {
        float v = has_pred ? pred[k] : 1.0f;
        out[c * CPC + k] = am ? v : 0.0f;
    }

    // reductions: num_active, num_predicted (active & has_pred), prev sum
    float na = am ? 1.f : 0.f;
    float np = (am && has_pred) ? 1.f : 0.f;
    float ps = 0.f;
#pragma unroll
    for (int k = 0; k < CPC; k++) ps += prev_active[c * CPC + k];

#pragma unroll
    for (int off = 16; off > 0; off >>= 1) {
        na += __shfl_down_sync(0xFFFFFFFFu, na, off);
        np += __shfl_down_sync(0xFFFFFFFFu, np, off);
        ps += __shfl_down_sync(0xFFFFFFFFu, ps, off);
    }
    __shared__ float s_na[32], s_np[32], s_ps[32];
    int w = threadIdx.x >> 5, l = threadIdx.x & 31;
    if (l == 0) { s_na[w] = na; s_np[w] = np; s_ps[w] = ps; }
    __syncthreads();
    if (w == 0) {
        na = s_na[l]; np = s_np[l]; ps = s_ps[l];
#pragma unroll
        for (int off = 16; off > 0; off >>= 1) {
            na += __shfl_down_sync(0xFFFFFFFFu, na, off);
            np += __shfl_down_sync(0xFFFFFFFFu, np, off);
            ps += __shfl_down_sync(0xFFFFFFFFu, ps, off);
        }
        if (l == 0) {
            float denom = fmaxf(na, 1.0f);
            out[2 * NCELLS] = 1.0f - np / denom;   // anomaly
            g_prev_has = (ps > 0.f) ? 1 : 0;
        }
    }
}

// ---------------------------------------------------------------------------
// K2: fused matvec (connected @ new_active) + permanence update, one pass
// over the 256 MB weight matrix. One block per row, 256 threads, each thread
// handles 8 float4 chunks (32 elements). W loads are 16B aligned; output
// weight region starts at float offset 16385 -> scalar stores only.
// ---------------------------------------------------------------------------
__global__ __launch_bounds__(256) void tm_row_kernel(
    const float* __restrict__ W,
    const float* __restrict__ prev_active,
    float* __restrict__ out) {
    const int r = blockIdx.x;
    const int t = threadIdx.x;

    const float* __restrict__ a = out;                 // new_active
    float* __restrict__ pred_out = out + NCELLS;
    float* __restrict__ w_out = out + 2 * NCELLS + 1;  // offset 16385

    const float4* __restrict__ wrow =
        reinterpret_cast<const float4*>(W + (size_t)r * NCELLS);
    const float4* __restrict__ a4p = reinterpret_cast<const float4*>(a);
    float* __restrict__ orow = w_out + (size_t)r * NCELLS;

    const float p = prev_active[r] * (float)g_prev_has;

    float acc = 0.f;

    if (p != 0.f) {
#pragma unroll
        for (int i = 0; i < 8; i++) {
            int idx = t + i * 256;
            float4 w4 = wrow[idx];
            float4 a4 = a4p[idx];
            acc += (w4.x >= PERM_CONN ? a4.x : 0.f)
                 + (w4.y >= PERM_CONN ? a4.y : 0.f)
                 + (w4.z >= PERM_CONN ? a4.z : 0.f)
                 + (w4.w >= PERM_CONN ? a4.w : 0.f);
            // delta = 0.1*a, decay = 0.01*(1-a); p == 1 here (binary input)
            float ox = fminf(fmaxf(w4.x + (0.1f * a4.x - 0.01f * (1.f - a4.x)) * p, 0.f), 1.f);
            float oy = fminf(fmaxf(w4.y + (0.1f * a4.y - 0.01f * (1.f - a4.y)) * p, 0.f), 1.f);
            float oz = fminf(fmaxf(w4.z + (0.1f * a4.z - 0.01f * (1.f - a4.z)) * p, 0.f), 1.f);
            float ow = fminf(fmaxf(w4.w + (0.1f * a4.w - 0.01f * (1.f - a4.w)) * p, 0.f), 1.f);
            int j = idx * 4;
            orow[j + 0] = ox;
            orow[j + 1] = oy;
            orow[j + 2] = oz;
            orow[j + 3] = ow;
        }
    } else {
#pragma unroll
        for (int i = 0; i < 8; i++) {
            int idx = t + i * 256;
            float4 w4 = wrow[idx];
            float4 a4 = a4p[idx];
            acc += (w4.x >= PERM_CONN ? a4.x : 0.f)
                 + (w4.y >= PERM_CONN ? a4.y : 0.f)
                 + (w4.z >= PERM_CONN ? a4.z : 0.f)
                 + (w4.w >= PERM_CONN ? a4.w : 0.f);
            int j = idx * 4;
            orow[j + 0] = w4.x;
            orow[j + 1] = w4.y;
            orow[j + 2] = w4.z;
            orow[j + 3] = w4.w;
        }
    }

    // block reduction of acc -> presyn[r]
#pragma unroll
    for (int off = 16; off > 0; off >>= 1)
        acc += __shfl_down_sync(0xFFFFFFFFu, acc, off);
    __shared__ float sacc[8];
    int w = t >> 5, l = t & 31;
    if (l == 0) sacc[w] = acc;
    __syncthreads();
    if (t == 0) {
        float s = 0.f;
#pragma unroll
        for (int i = 0; i < 8; i++) s += sacc[i];
        pred_out[r] = (s >= THRESH) ? 1.0f : 0.0f;
    }
}

extern "C" void kernel_launch(void* const* d_in, const int* in_sizes, int n_in,
                              void* d_out, int out_size) {
    const float* active_columns  = (const float*)d_in[0];
    const float* segment_weights = (const float*)d_in[1];
    const float* predictive      = (const float*)d_in[2];
    const float* prev_active     = (const float*)d_in[3];
    float* out = (float*)d_out;

    tm_small_kernel<<<1, COLS>>>(active_columns, predictive, prev_active, out);
    tm_row_kernel<<<NCELLS, 256>>>(segment_weights, prev_active, out);
}